// round 14
// baseline (speedup 1.0000x reference)
#include <cuda_runtime.h>
#include <cuda_fp16.h>
#include <cstdint>
#include <math.h>

// Problem constants
#define BSZ 4
#define SEQ 2048
#define DMODEL 1024
#define NHEADS 16
#define DHEAD 64
#define QKVCOLS (3 * DMODEL)          // 3072
#define MROWS (BSZ * SEQ)             // 8192

// Scratch (device globals)
__device__ __half g_xh    [(size_t)MROWS * DMODEL];    // x, fp16
__device__ __half g_qkh   [(size_t)MROWS * 2 * DMODEL];// Q,K fp16 [row][0..2047]
__device__ __half g_attnh [(size_t)MROWS * DMODEL];    // attn out, fp16
__device__ __half g_wqkvTh[(size_t)QKVCOLS * DMODEL];  // W_qkv^T, fp16
__device__ __half g_woutTh[(size_t)DMODEL * DMODEL];   // W_out^T, fp16
__device__ __half g_vh    [(size_t)BSZ * NHEADS * DHEAD * SEQ]; // V^T fp16 [b][h][d][t]

// ---------------------------------------------------------------------------
// Helpers
// ---------------------------------------------------------------------------
__device__ __forceinline__ uint32_t smem_u32(const void* p) {
    uint32_t a;
    asm("{ .reg .u64 t; cvta.to.shared.u64 t, %1; cvt.u32.u64 %0, t; }"
        : "=r"(a) : "l"(p));
    return a;
}
__device__ __forceinline__ uint32_t pack_h2(float a, float b) {
    __half2 h = __floats2half2_rn(a, b);
    return *reinterpret_cast<uint32_t*>(&h);
}

#define CP_ASYNC16(dst_u32, src_ptr) \
    asm volatile("cp.async.ca.shared.global [%0], [%1], 16;" \
                 :: "r"(dst_u32), "l"(src_ptr) : "memory")
#define CP_COMMIT() asm volatile("cp.async.commit_group;" ::: "memory")
#define CP_WAIT_1() asm volatile("cp.async.wait_group 1;" ::: "memory")
#define CP_WAIT_0() asm volatile("cp.async.wait_group 0;" ::: "memory")

__device__ __forceinline__ void ldm_x4(uint32_t* r, uint32_t addr) {
    asm volatile("ldmatrix.sync.aligned.m8n8.x4.shared.b16 {%0,%1,%2,%3}, [%4];"
        : "=r"(r[0]), "=r"(r[1]), "=r"(r[2]), "=r"(r[3]) : "r"(addr));
}

// fp16 m16n8k16, f32 accumulate
__device__ __forceinline__ void mma16816h(float* d, const uint32_t* a,
                                          uint32_t b0, uint32_t b1) {
    asm volatile(
        "mma.sync.aligned.m16n8k16.row.col.f32.f16.f16.f32 "
        "{%0,%1,%2,%3}, {%4,%5,%6,%7}, {%8,%9}, {%0,%1,%2,%3};"
        : "+f"(d[0]), "+f"(d[1]), "+f"(d[2]), "+f"(d[3])
        : "r"(a[0]), "r"(a[1]), "r"(a[2]), "r"(a[3]), "r"(b0), "r"(b1));
}

// ---------------------------------------------------------------------------
// fp16 GEMM: C[M,N] = A[M,K] * Bt[N,K]^T, f32 accumulate.
// CTA tile 64x128, BK=64, 2-stage cp.async double buffer (R9 structure).
// 8 warps, each 32x32 (acc=32 regs) -> __launch_bounds__(256,3) gives
// 24 warps/SM (vs 16 before) for latency hiding.
// mode 0: f32 out. mode 1: QKV (cols<2048 -> fp16 Q/K; >=2048 -> fp16 V^T).
// ---------------------------------------------------------------------------
#define GSTR 72
#define ABUF (64 * GSTR * 2)          // 9216 bytes (A: 64 rows)
#define BBUF (128 * GSTR * 2)         // 18432 bytes (B: 128 rows)
#define GSTAGE (ABUF + BBUF)          // 27648
#define GEMM_SMEM (2 * GSTAGE)        // 55296

__global__ void __launch_bounds__(256, 3) gemm_fp16_kernel(
    const __half* __restrict__ A, const __half* __restrict__ Bt,
    float* __restrict__ C, __half* __restrict__ qkh, __half* __restrict__ vh,
    int M, int N, int K, int mode)
{
    extern __shared__ char smem[];
    const int tid = threadIdx.x, wid = tid >> 5, lane = tid & 31;
    const int rowBase = blockIdx.y << 6, colBase = blockIdx.x << 7;
    const uint32_t sb = smem_u32(smem);

    const int wr = wid >> 2, wc = wid & 3;         // 2 x 4 warp grid
    const int q = lane >> 2, cc = lane & 3;

    const int ar = (lane & 7) + ((lane >> 3) & 1) * 8;  // A: {r,r+8} x {k,k+8}
    const int ac = (lane >> 4) * 8;
    const int br = (lane & 7) + (lane >> 4) * 8;        // B: {n,n+8} x {k,k+8}
    const int bc = ((lane >> 3) & 1) * 8;

    float acc[2][4][4];
#pragma unroll
    for (int a = 0; a < 2; ++a)
#pragma unroll
        for (int b = 0; b < 4; ++b)
#pragma unroll
            for (int r = 0; r < 4; ++r) acc[a][b][r] = 0.0f;

    const int nchunks = K >> 6;

    auto load_tile = [&](int c, int buf) {
        const int k0 = c << 6;
        const uint32_t base = sb + (uint32_t)buf * GSTAGE;
#pragma unroll
        for (int i = 0; i < 2; ++i) {
            const int f   = tid + i * 256;         // 0..511
            const int row = f >> 3;                // 0..63
            const int c8  = (f & 7) << 3;
            CP_ASYNC16(base + (row * GSTR + c8) * 2,
                       &A[(size_t)(rowBase + row) * K + k0 + c8]);
        }
#pragma unroll
        for (int i = 0; i < 4; ++i) {
            const int f   = tid + i * 256;         // 0..1023
            const int row = f >> 3;                // 0..127
            const int c8  = (f & 7) << 3;
            CP_ASYNC16(base + ABUF + (row * GSTR + c8) * 2,
                       &Bt[(size_t)(colBase + row) * K + k0 + c8]);
        }
        CP_COMMIT();
    };

    load_tile(0, 0);

    for (int c = 0; c < nchunks; ++c) {
        const int buf = c & 1;
        if (c + 1 < nchunks) { load_tile(c + 1, (c + 1) & 1); CP_WAIT_1(); }
        else                 { CP_WAIT_0(); }
        __syncthreads();

        const uint32_t stg = sb + (uint32_t)buf * GSTAGE;
        const uint32_t aAddr = stg + ((wr * 32 + ar) * GSTR + ac) * 2;
        const uint32_t bAddr = stg + ABUF + ((wc * 32 + br) * GSTR + bc) * 2;

#pragma unroll
        for (int ks = 0; ks < 4; ++ks) {
            uint32_t bfr[2][4];
#pragma unroll
            for (int nh = 0; nh < 2; ++nh)
                ldm_x4(bfr[nh], bAddr + (nh * 16 * GSTR + ks * 16) * 2);
#pragma unroll
            for (int mt = 0; mt < 2; ++mt) {
                uint32_t af[4];
                ldm_x4(af, aAddr + (mt * 16 * GSTR + ks * 16) * 2);
                mma16816h(acc[mt][0], af, bfr[0][0], bfr[0][1]);
                mma16816h(acc[mt][1], af, bfr[0][2], bfr[0][3]);
                mma16816h(acc[mt][2], af, bfr[1][0], bfr[1][1]);
                mma16816h(acc[mt][3], af, bfr[1][2], bfr[1][3]);
            }
        }
        __syncthreads();
    }

    // Epilogue
#pragma unroll
    for (int mt = 0; mt < 2; ++mt) {
        const int row0 = rowBase + wr * 32 + mt * 16 + q;
#pragma unroll
        for (int nt = 0; nt < 4; ++nt) {
            const int grp = colBase + wc * 32 + nt * 8;
            if (mode == 0) {
                *reinterpret_cast<float2*>(&C[(size_t)row0 * N + grp + 2 * cc]) =
                    make_float2(acc[mt][nt][0], acc[mt][nt][1]);
                *reinterpret_cast<float2*>(&C[(size_t)(row0 + 8) * N + grp + 2 * cc]) =
                    make_float2(acc[mt][nt][2], acc[mt][nt][3]);
            } else if (grp < 2048) {
                *reinterpret_cast<uint32_t*>(
                    &qkh[(size_t)row0 * 2048 + grp + 2 * cc]) =
                    pack_h2(acc[mt][nt][0], acc[mt][nt][1]);
                *reinterpret_cast<uint32_t*>(
                    &qkh[(size_t)(row0 + 8) * 2048 + grp + 2 * cc]) =
                    pack_h2(acc[mt][nt][2], acc[mt][nt][3]);
            } else {
                const int dg = grp - 2048 + 2 * cc;
                const int h = dg >> 6, d = dg & 63;
                const int b0r = row0 >> 11, t0 = row0 & 2047;
                __half* vb = vh + ((size_t)(b0r * NHEADS + h) * DHEAD) * SEQ;
                vb[(size_t)d * SEQ + t0]           = __float2half(acc[mt][nt][0]);
                vb[(size_t)(d + 1) * SEQ + t0]     = __float2half(acc[mt][nt][1]);
                vb[(size_t)d * SEQ + t0 + 8]       = __float2half(acc[mt][nt][2]);
                vb[(size_t)(d + 1) * SEQ + t0 + 8] = __float2half(acc[mt][nt][3]);
            }
        }
    }
}

// ---------------------------------------------------------------------------
// Pre-passes
// ---------------------------------------------------------------------------
__global__ void __launch_bounds__(256) cvt_fp16_kernel(
    const float4* __restrict__ in, uint2* __restrict__ out, int n8)
{
    int i = blockIdx.x * blockDim.x + threadIdx.x;
    if (i < n8) {
        float4 a = in[2 * i], b = in[2 * i + 1];
        uint2 o, o2;
        o.x = pack_h2(a.x, a.y);  o.y = pack_h2(a.z, a.w);
        o2.x = pack_h2(b.x, b.y); o2.y = pack_h2(b.z, b.w);
        out[2 * i] = o; out[2 * i + 1] = o2;
    }
}

__global__ void __launch_bounds__(256) transpose_fp16_kernel(
    const float* __restrict__ W, __half* __restrict__ Wt, int K, int N)
{
    __shared__ float t[32][33];
    const int n0 = blockIdx.x * 32, k0 = blockIdx.y * 32;
    const int tx = threadIdx.x, ty = threadIdx.y;   // 32 x 8
#pragma unroll
    for (int i = 0; i < 4; ++i)
        t[ty + i * 8][tx] = W[(size_t)(k0 + ty + i * 8) * N + n0 + tx];
    __syncthreads();
#pragma unroll
    for (int i = 0; i < 4; ++i)
        Wt[(size_t)(n0 + ty + i * 8) * K + k0 + tx] = __float2half(t[tx][ty + i * 8]);
}

// ---------------------------------------------------------------------------
// Tensor-core causal flash attention — all fp16 MMAs, f32 softmax/accum.
// R9 structure (2-stage double buffer, two barriers per KV tile) + LPT
// (longest CTAs launch first). Grid (16 q-tiles x 128, 16 heads, 4 batch).
// ---------------------------------------------------------------------------
#define STR 72
#define TBUF (64 * STR * 2)           // bytes per 64x64 fp16 buffer = 9216
#define ATTN_SMEM (4 * TBUF)          // 36864

__global__ void __launch_bounds__(256) attn_mma_kernel(
    const __half* __restrict__ qkh, const __half* __restrict__ vh,
    __half* __restrict__ out)
{
    extern __shared__ char smc[];

    const int tid = threadIdx.x, wq = tid >> 5, lane = tid & 31;
    const int q = lane >> 2, cc = lane & 3;
    const int rt = gridDim.x - 1 - blockIdx.x;       // longest first
    const int h = blockIdx.y, b = blockIdx.z;
    const int qb = rt * 128;
    const int nkt = 2 * rt + 2;
    const __half* base = qkh + (size_t)b * SEQ * 2048;
    const __half* vbase = vh + ((size_t)(b * NHEADS + h) * DHEAD) * SEQ;
    const uint32_t smb = smem_u32(smc);

    const int brow = (lane & 7) + (lane >> 4) * 8;
    const int bcol = ((lane >> 3) & 1) * 8;     // halves

    // Resident Q a-frags (fp16, scaled by 1/8 exactly)
    uint32_t aq[4][4];
    {
        const int r0 = qb + wq * 16 + q;
        const __half2 s8 = __half2half2(__float2half(0.125f));
#pragma unroll
        for (int ks = 0; ks < 4; ++ks)
#pragma unroll
            for (int e = 0; e < 4; ++e) {
                const int row = r0 + (e & 1) * 8;
                const int col = h * DHEAD + 16 * ks + 2 * cc + (e >> 1) * 8;
                __half2 v = *reinterpret_cast<const __half2*>(
                    &base[(size_t)row * 2048 + col]);
                v = __hmul2(v, s8);
                aq[ks][e] = *reinterpret_cast<uint32_t*>(&v);
            }
    }

    float oacc[8][4];
#pragma unroll
    for (int nt = 0; nt < 8; ++nt)
#pragma unroll
        for (int e = 0; e < 4; ++e) oacc[nt][e] = 0.0f;
    float m0 = -INFINITY, m1 = -INFINITY, l0 = 0.0f, l1 = 0.0f;

    auto cptile = [&](int kt, int bufsel) {
        const __half* kS = base + (size_t)(kt * 64) * 2048 + 1024 + h * DHEAD;
        const uint32_t kD = smb + (uint32_t)bufsel * TBUF;
#pragma unroll
        for (int i = 0; i < 2; ++i) {
            const int ch = tid + i * 256;
            const int row = ch >> 3;
            const int c8  = (ch & 7) << 3;
            CP_ASYNC16(kD + (row * STR + c8) * 2, kS + (size_t)row * 2048 + c8);
        }
        const __half* vS = vbase + kt * 64;
        const uint32_t vD = smb + 2 * TBUF + (uint32_t)bufsel * TBUF;
#pragma unroll
        for (int i = 0; i < 2; ++i) {
            const int ch = tid + i * 256;
            const int d  = ch >> 3;
            const int c8 = (ch & 7) << 3;
            CP_ASYNC16(vD + (d * STR + c8) * 2, vS + (size_t)d * SEQ + c8);
        }
        CP_COMMIT();
    };

    cptile(0, 0);

    for (int kt = 0; kt < nkt; ++kt) {
        const int buf = kt & 1;
        if (kt + 1 < nkt) { cptile(kt + 1, (kt + 1) & 1); CP_WAIT_1(); }
        else              { CP_WAIT_0(); }
        __syncthreads();

        const uint32_t kAddr = smb + (uint32_t)buf * TBUF + (brow * STR + bcol) * 2;
        const uint32_t vAddr = smb + 2 * TBUF + (uint32_t)buf * TBUF
                             + (brow * STR + bcol) * 2;

        // ---- S = (Q/8) K^T ----
        float sacc[8][4];
#pragma unroll
        for (int hh = 0; hh < 4; ++hh) {
            sacc[2*hh][0] = sacc[2*hh][1] = sacc[2*hh][2] = sacc[2*hh][3] = 0.0f;
            sacc[2*hh+1][0] = sacc[2*hh+1][1] = sacc[2*hh+1][2] = sacc[2*hh+1][3] = 0.0f;
#pragma unroll
            for (int ks = 0; ks < 4; ++ks) {
                uint32_t kb[4];
                ldm_x4(kb, kAddr + (hh * 16 * STR + ks * 16) * 2);
                mma16816h(sacc[2 * hh],     aq[ks], kb[0], kb[1]);
                mma16816h(sacc[2 * hh + 1], aq[ks], kb[2], kb[3]);
            }
        }

        // ---- causal mask ----
        if (kt * 64 + 63 > qb + wq * 16) {
            const int r0g = qb + wq * 16 + q, r1g = r0g + 8;
#pragma unroll
            for (int nt = 0; nt < 8; ++nt) {
                const int c0g = kt * 64 + 8 * nt + 2 * cc;
                if (c0g     > r0g) sacc[nt][0] = -INFINITY;
                if (c0g + 1 > r0g) sacc[nt][1] = -INFINITY;
                if (c0g     > r1g) sacc[nt][2] = -INFINITY;
                if (c0g + 1 > r1g) sacc[nt][3] = -INFINITY;
            }
        }

        // ---- online softmax ----
        float cm0 = -INFINITY, cm1 = -INFINITY;
#pragma unroll
        for (int nt = 0; nt < 8; ++nt) {
            cm0 = fmaxf(cm0, fmaxf(sacc[nt][0], sacc[nt][1]));
            cm1 = fmaxf(cm1, fmaxf(sacc[nt][2], sacc[nt][3]));
        }
        cm0 = fmaxf(cm0, __shfl_xor_sync(0xffffffffu, cm0, 1));
        cm0 = fmaxf(cm0, __shfl_xor_sync(0xffffffffu, cm0, 2));
        cm1 = fmaxf(cm1, __shfl_xor_sync(0xffffffffu, cm1, 1));
        cm1 = fmaxf(cm1, __shfl_xor_sync(0xffffffffu, cm1, 2));

        const float mn0 = fmaxf(m0, cm0), mn1 = fmaxf(m1, cm1);
        const float corr0 = __expf(m0 - mn0), corr1 = __expf(m1 - mn1);

        uint32_t ph[8][2];
        float ps0 = 0.0f, ps1 = 0.0f;
#pragma unroll
        for (int nt = 0; nt < 8; ++nt) {
            const float pp0 = __expf(sacc[nt][0] - mn0);
            const float pp1 = __expf(sacc[nt][1] - mn0);
            const float pp2 = __expf(sacc[nt][2] - mn1);
            const float pp3 = __expf(sacc[nt][3] - mn1);
            ps0 += pp0 + pp1; ps1 += pp2 + pp3;
            ph[nt][0] = pack_h2(pp0, pp1);
            ph[nt][1] = pack_h2(pp2, pp3);
            oacc[nt][0] *= corr0; oacc[nt][1] *= corr0;
            oacc[nt][2] *= corr1; oacc[nt][3] *= corr1;
        }
        l0 = l0 * corr0 + ps0;
        l1 = l1 * corr1 + ps1;
        m0 = mn0; m1 = mn1;

        // ---- O += P V ----
#pragma unroll
        for (int g = 0; g < 4; ++g) {
            uint32_t ap[4] = { ph[2 * g][0], ph[2 * g][1],
                               ph[2 * g + 1][0], ph[2 * g + 1][1] };
#pragma unroll
            for (int hh = 0; hh < 4; ++hh) {
                uint32_t vb4[4];
                ldm_x4(vb4, vAddr + (hh * 16 * STR + g * 16) * 2);
                mma16816h(oacc[2 * hh],     ap, vb4[0], vb4[1]);
                mma16816h(oacc[2 * hh + 1], ap, vb4[2], vb4[3]);
            }
        }
        __syncthreads();
    }

    // ---- epilogue: fp16 output ----
    l0 += __shfl_xor_sync(0xffffffffu, l0, 1);
    l0 += __shfl_xor_sync(0xffffffffu, l0, 2);
    l1 += __shfl_xor_sync(0xffffffffu, l1, 1);
    l1 += __shfl_xor_sync(0xffffffffu, l1, 2);
    const float inv0 = 1.0f / l0, inv1 = 1.0f / l1;

    __half* ob = out + (size_t)(b * SEQ + qb + wq * 16 + q) * DMODEL + h * DHEAD;
#pragma unroll
    for (int nt = 0; nt < 8; ++nt) {
        *reinterpret_cast<uint32_t*>(&ob[8 * nt + 2 * cc]) =
            pack_h2(oacc[nt][0] * inv0, oacc[nt][1] * inv0);
        *reinterpret_cast<uint32_t*>(&ob[(size_t)8 * DMODEL + 8 * nt + 2 * cc]) =
            pack_h2(oacc[nt][2] * inv1, oacc[nt][3] * inv1);
    }
}

// ---------------------------------------------------------------------------
extern "C" void kernel_launch(void* const* d_in, const int* in_sizes, int n_in,
                              void* d_out, int out_size)
{
    const float* x     = (const float*)d_in[0];
    const float* W_qkv = (const float*)d_in[1];
    const float* W_out = (const float*)d_in[2];
    float* out = (float*)d_out;

    __half *xh, *qkh, *attnh, *wqkvTh, *woutTh, *vh;
    cudaGetSymbolAddress((void**)&xh,     g_xh);
    cudaGetSymbolAddress((void**)&qkh,    g_qkh);
    cudaGetSymbolAddress((void**)&attnh,  g_attnh);
    cudaGetSymbolAddress((void**)&wqkvTh, g_wqkvTh);
    cudaGetSymbolAddress((void**)&woutTh, g_woutTh);
    cudaGetSymbolAddress((void**)&vh,     g_vh);

    cudaFuncSetAttribute(gemm_fp16_kernel,
                         cudaFuncAttributeMaxDynamicSharedMemorySize, GEMM_SMEM);
    cudaFuncSetAttribute(attn_mma_kernel,
                         cudaFuncAttributeMaxDynamicSharedMemorySize, ATTN_SMEM);

    // Pre-passes
    const int n8 = MROWS * DMODEL / 8;
    cvt_fp16_kernel<<<n8 / 256, 256>>>((const float4*)x, (uint2*)xh, n8);
    transpose_fp16_kernel<<<dim3(QKVCOLS / 32, DMODEL / 32), dim3(32, 8)>>>(
        W_qkv, wqkvTh, DMODEL, QKVCOLS);
    transpose_fp16_kernel<<<dim3(DMODEL / 32, DMODEL / 32), dim3(32, 8)>>>(
        W_out, woutTh, DMODEL, DMODEL);

    // 1) QKV projection (fp16 MMA): fp16 Q/K + fp16 V^T
    gemm_fp16_kernel<<<dim3(QKVCOLS / 128, MROWS / 64), 256, GEMM_SMEM>>>(
        xh, wqkvTh, nullptr, qkh, vh, MROWS, QKVCOLS, DMODEL, 1);

    // 2) Flash attention (fp16 QK^T + fp16 PV) -> fp16 out
    attn_mma_kernel<<<dim3(SEQ / 128, NHEADS, BSZ), 256, ATTN_SMEM>>>(qkh, vh, attnh);

    // 3) Output projection (fp16 MMA) -> f32 result
    gemm_fp16_kernel<<<dim3(DMODEL / 128, MROWS / 64), 256, GEMM_SMEM>>>(
        attnh, woutTh, out, nullptr, nullptr, MROWS, DMODEL, DMODEL, 0);
}

// round 16
// speedup vs baseline: 1.0488x; 1.0488x over previous
#include <cuda_runtime.h>
#include <cuda_fp16.h>
#include <cstdint>
#include <math.h>

// Problem constants
#define BSZ 4
#define SEQ 2048
#define DMODEL 1024
#define NHEADS 16
#define DHEAD 64
#define QKVCOLS (3 * DMODEL)          // 3072
#define MROWS (BSZ * SEQ)             // 8192

// Scratch (device globals)
__device__ __half g_xh    [(size_t)MROWS * DMODEL];    // x, fp16
__device__ __half g_qkh   [(size_t)MROWS * 2 * DMODEL];// Q,K fp16 [row][0..2047]
__device__ __half g_attnh [(size_t)MROWS * DMODEL];    // attn out, fp16
__device__ __half g_wqkvTh[(size_t)QKVCOLS * DMODEL];  // W_qkv^T, fp16
__device__ __half g_woutTh[(size_t)DMODEL * DMODEL];   // W_out^T, fp16
__device__ __half g_vh    [(size_t)BSZ * NHEADS * SEQ * DHEAD]; // V fp16 [b][h][t][d]

// ---------------------------------------------------------------------------
// Helpers
// ---------------------------------------------------------------------------
__device__ __forceinline__ uint32_t smem_u32(const void* p) {
    uint32_t a;
    asm("{ .reg .u64 t; cvta.to.shared.u64 t, %1; cvt.u32.u64 %0, t; }"
        : "=r"(a) : "l"(p));
    return a;
}
__device__ __forceinline__ uint32_t pack_h2(float a, float b) {
    __half2 h = __floats2half2_rn(a, b);
    return *reinterpret_cast<uint32_t*>(&h);
}

#define CP_ASYNC16(dst_u32, src_ptr) \
    asm volatile("cp.async.ca.shared.global [%0], [%1], 16;" \
                 :: "r"(dst_u32), "l"(src_ptr) : "memory")
#define CP_COMMIT() asm volatile("cp.async.commit_group;" ::: "memory")
#define CP_WAIT_1() asm volatile("cp.async.wait_group 1;" ::: "memory")
#define CP_WAIT_0() asm volatile("cp.async.wait_group 0;" ::: "memory")

__device__ __forceinline__ void ldm_x4(uint32_t* r, uint32_t addr) {
    asm volatile("ldmatrix.sync.aligned.m8n8.x4.shared.b16 {%0,%1,%2,%3}, [%4];"
        : "=r"(r[0]), "=r"(r[1]), "=r"(r[2]), "=r"(r[3]) : "r"(addr));
}
// Transposing variant: loads 8x8 b16 tiles and transposes into b-frag layout.
__device__ __forceinline__ void ldm_x4_t(uint32_t* r, uint32_t addr) {
    asm volatile("ldmatrix.sync.aligned.m8n8.x4.trans.shared.b16 {%0,%1,%2,%3}, [%4];"
        : "=r"(r[0]), "=r"(r[1]), "=r"(r[2]), "=r"(r[3]) : "r"(addr));
}

// fp16 m16n8k16, f32 accumulate
__device__ __forceinline__ void mma16816h(float* d, const uint32_t* a,
                                          uint32_t b0, uint32_t b1) {
    asm volatile(
        "mma.sync.aligned.m16n8k16.row.col.f32.f16.f16.f32 "
        "{%0,%1,%2,%3}, {%4,%5,%6,%7}, {%8,%9}, {%0,%1,%2,%3};"
        : "+f"(d[0]), "+f"(d[1]), "+f"(d[2]), "+f"(d[3])
        : "r"(a[0]), "r"(a[1]), "r"(a[2]), "r"(a[3]), "r"(b0), "r"(b1));
}

// ---------------------------------------------------------------------------
// fp16 GEMM (R9 champion shape): C[M,N] = A[M,K] * Bt[N,K]^T, f32 accum.
// 128x128 CTA tiles, BK=64, 2-stage cp.async double buffer, 8 warps 64x32.
// mode 0: f32 out. mode 1: QKV (cols<2048 -> fp16 Q/K; >=2048 -> fp16 V
// in natural [b][h][t][d] layout, packed coalesced stores).
// ---------------------------------------------------------------------------
#define GSTR 72
#define GBUF (128 * GSTR * 2)         // bytes per matrix buffer = 18432
#define GEMM_SMEM (4 * GBUF)          // 73728 (A0,A1,B0,B1)

__global__ void __launch_bounds__(256) gemm_fp16_kernel(
    const __half* __restrict__ A, const __half* __restrict__ Bt,
    float* __restrict__ C, __half* __restrict__ qkh, __half* __restrict__ vh,
    int M, int N, int K, int mode)
{
    extern __shared__ char smem[];
    const int tid = threadIdx.x, wid = tid >> 5, lane = tid & 31;
    const int rowBase = blockIdx.y << 7, colBase = blockIdx.x << 7;
    const uint32_t sb = smem_u32(smem);

    const int wr = wid >> 2, wc = wid & 3;
    const int q = lane >> 2, cc = lane & 3;

    const int ar = (lane & 7) + ((lane >> 3) & 1) * 8;  // A: {r,r+8} x {k,k+8}
    const int ac = (lane >> 4) * 8;
    const int br = (lane & 7) + (lane >> 4) * 8;        // B: {n,n+8} x {k,k+8}
    const int bc = ((lane >> 3) & 1) * 8;

    float acc[4][4][4];
#pragma unroll
    for (int a = 0; a < 4; ++a)
#pragma unroll
        for (int b = 0; b < 4; ++b)
#pragma unroll
            for (int r = 0; r < 4; ++r) acc[a][b][r] = 0.0f;

    const int nchunks = K >> 6;

    auto load_tile = [&](int c, int buf) {
        const int k0 = c << 6;
#pragma unroll
        for (int i = 0; i < 4; ++i) {
            const int f   = tid + i * 256;
            const int row = f >> 3;
            const int c8  = (f & 7) << 3;
            CP_ASYNC16(sb + buf * GBUF + (row * GSTR + c8) * 2,
                       &A[(size_t)(rowBase + row) * K + k0 + c8]);
            CP_ASYNC16(sb + 2 * GBUF + buf * GBUF + (row * GSTR + c8) * 2,
                       &Bt[(size_t)(colBase + row) * K + k0 + c8]);
        }
        CP_COMMIT();
    };

    load_tile(0, 0);

    for (int c = 0; c < nchunks; ++c) {
        const int buf = c & 1;
        if (c + 1 < nchunks) { load_tile(c + 1, (c + 1) & 1); CP_WAIT_1(); }
        else                 { CP_WAIT_0(); }
        __syncthreads();

        const uint32_t aAddr = sb + buf * GBUF + ((wr * 64 + ar) * GSTR + ac) * 2;
        const uint32_t bAddr = sb + 2 * GBUF + buf * GBUF
                             + ((wc * 32 + br) * GSTR + bc) * 2;

#pragma unroll
        for (int ks = 0; ks < 4; ++ks) {
            uint32_t bfr[2][4];
#pragma unroll
            for (int nh = 0; nh < 2; ++nh)
                ldm_x4(bfr[nh], bAddr + (nh * 16 * GSTR + ks * 16) * 2);
#pragma unroll
            for (int mt = 0; mt < 4; ++mt) {
                uint32_t af[4];
                ldm_x4(af, aAddr + (mt * 16 * GSTR + ks * 16) * 2);
#pragma unroll
                for (int nh = 0; nh < 2; ++nh) {
                    mma16816h(acc[mt][2 * nh],     af, bfr[nh][0], bfr[nh][1]);
                    mma16816h(acc[mt][2 * nh + 1], af, bfr[nh][2], bfr[nh][3]);
                }
            }
        }
        __syncthreads();
    }

    // Epilogue
#pragma unroll
    for (int mt = 0; mt < 4; ++mt) {
        const int row0 = rowBase + wr * 64 + mt * 16 + q;
#pragma unroll
        for (int nt = 0; nt < 4; ++nt) {
            const int grp = colBase + wc * 32 + nt * 8;
            if (mode == 0) {
                *reinterpret_cast<float2*>(&C[(size_t)row0 * N + grp + 2 * cc]) =
                    make_float2(acc[mt][nt][0], acc[mt][nt][1]);
                *reinterpret_cast<float2*>(&C[(size_t)(row0 + 8) * N + grp + 2 * cc]) =
                    make_float2(acc[mt][nt][2], acc[mt][nt][3]);
            } else if (grp < 2048) {
                *reinterpret_cast<uint32_t*>(
                    &qkh[(size_t)row0 * 2048 + grp + 2 * cc]) =
                    pack_h2(acc[mt][nt][0], acc[mt][nt][1]);
                *reinterpret_cast<uint32_t*>(
                    &qkh[(size_t)(row0 + 8) * 2048 + grp + 2 * cc]) =
                    pack_h2(acc[mt][nt][2], acc[mt][nt][3]);
            } else {
                // V region -> natural [b][h][t][d], packed 4B coalesced stores
                const int dg = grp - 2048 + 2 * cc;
                const int h = dg >> 6, d = dg & 63;
                const int b0r = row0 >> 11, t0 = row0 & 2047;
                __half* vb = vh + ((size_t)(b0r * NHEADS + h) * SEQ) * DHEAD;
                *reinterpret_cast<uint32_t*>(&vb[(size_t)t0 * DHEAD + d]) =
                    pack_h2(acc[mt][nt][0], acc[mt][nt][1]);
                *reinterpret_cast<uint32_t*>(&vb[(size_t)(t0 + 8) * DHEAD + d]) =
                    pack_h2(acc[mt][nt][2], acc[mt][nt][3]);
            }
        }
    }
}

// ---------------------------------------------------------------------------
// Pre-passes
// ---------------------------------------------------------------------------
__global__ void __launch_bounds__(256) cvt_fp16_kernel(
    const float4* __restrict__ in, uint2* __restrict__ out, int n8)
{
    int i = blockIdx.x * blockDim.x + threadIdx.x;
    if (i < n8) {
        float4 a = in[2 * i], b = in[2 * i + 1];
        uint2 o, o2;
        o.x = pack_h2(a.x, a.y);  o.y = pack_h2(a.z, a.w);
        o2.x = pack_h2(b.x, b.y); o2.y = pack_h2(b.z, b.w);
        out[2 * i] = o; out[2 * i + 1] = o2;
    }
}

__global__ void __launch_bounds__(256) transpose_fp16_kernel(
    const float* __restrict__ W, __half* __restrict__ Wt, int K, int N)
{
    __shared__ float t[32][33];
    const int n0 = blockIdx.x * 32, k0 = blockIdx.y * 32;
    const int tx = threadIdx.x, ty = threadIdx.y;   // 32 x 8
#pragma unroll
    for (int i = 0; i < 4; ++i)
        t[ty + i * 8][tx] = W[(size_t)(k0 + ty + i * 8) * N + n0 + tx];
    __syncthreads();
#pragma unroll
    for (int i = 0; i < 4; ++i)
        Wt[(size_t)(n0 + ty + i * 8) * K + k0 + tx] = __float2half(t[tx][ty + i * 8]);
}

// ---------------------------------------------------------------------------
// Tensor-core causal flash attention — all fp16 MMAs, f32 softmax/accum.
// R9 structure (2-stage, two barriers per KV tile) + LPT. V now loaded from
// natural [b][h][t][d] (contiguous 8KB tiles) and fragmented via
// ldmatrix.x4.trans. Grid (16 q-tiles x 128, 16 heads, 4 batch), 8 warps.
// ---------------------------------------------------------------------------
#define STR 72
#define TBUF (64 * STR * 2)           // bytes per 64x64 fp16 buffer = 9216
#define ATTN_SMEM (4 * TBUF)          // 36864

__global__ void __launch_bounds__(256) attn_mma_kernel(
    const __half* __restrict__ qkh, const __half* __restrict__ vh,
    __half* __restrict__ out)
{
    extern __shared__ char smc[];

    const int tid = threadIdx.x, wq = tid >> 5, lane = tid & 31;
    const int q = lane >> 2, cc = lane & 3;
    const int rt = gridDim.x - 1 - blockIdx.x;       // longest first (LPT)
    const int h = blockIdx.y, b = blockIdx.z;
    const int qb = rt * 128;
    const int nkt = 2 * rt + 2;
    const __half* base = qkh + (size_t)b * SEQ * 2048;
    const __half* vbase = vh + ((size_t)(b * NHEADS + h) * SEQ) * DHEAD;
    const uint32_t smb = smem_u32(smc);

    // K b-frag lane offsets (non-trans ldmatrix)
    const int brow = (lane & 7) + (lane >> 4) * 8;
    const int bcol = ((lane >> 3) & 1) * 8;     // halves
    // V b-frag lane offsets (trans ldmatrix on [t][d] tile):
    // groups: {t0-7,d0-7}, {t8-15,d0-7}, {t0-7,d8-15}, {t8-15,d8-15}
    const int vtr = (lane & 7) + ((lane >> 3) & 1) * 8;   // t within 16
    const int vdc = (lane >> 4) * 8;                      // d offset (halves)

    // Resident Q a-frags (fp16, scaled by 1/8 exactly)
    uint32_t aq[4][4];
    {
        const int r0 = qb + wq * 16 + q;
        const __half2 s8 = __half2half2(__float2half(0.125f));
#pragma unroll
        for (int ks = 0; ks < 4; ++ks)
#pragma unroll
            for (int e = 0; e < 4; ++e) {
                const int row = r0 + (e & 1) * 8;
                const int col = h * DHEAD + 16 * ks + 2 * cc + (e >> 1) * 8;
                __half2 v = *reinterpret_cast<const __half2*>(
                    &base[(size_t)row * 2048 + col]);
                v = __hmul2(v, s8);
                aq[ks][e] = *reinterpret_cast<uint32_t*>(&v);
            }
    }

    float oacc[8][4];
#pragma unroll
    for (int nt = 0; nt < 8; ++nt)
#pragma unroll
        for (int e = 0; e < 4; ++e) oacc[nt][e] = 0.0f;
    float m0 = -INFINITY, m1 = -INFINITY, l0 = 0.0f, l1 = 0.0f;

    auto cptile = [&](int kt, int bufsel) {
        // K: 64 t-rows x 64 halves (global row stride 2048)
        const __half* kS = base + (size_t)(kt * 64) * 2048 + 1024 + h * DHEAD;
        const uint32_t kD = smb + (uint32_t)bufsel * TBUF;
#pragma unroll
        for (int i = 0; i < 2; ++i) {
            const int ch = tid + i * 256;
            const int row = ch >> 3;
            const int c8  = (ch & 7) << 3;
            CP_ASYNC16(kD + (row * STR + c8) * 2, kS + (size_t)row * 2048 + c8);
        }
        // V: 64 t-rows x 64 halves — CONTIGUOUS 8KB block in global
        const __half* vS = vbase + (size_t)(kt * 64) * DHEAD;
        const uint32_t vD = smb + 2 * TBUF + (uint32_t)bufsel * TBUF;
#pragma unroll
        for (int i = 0; i < 2; ++i) {
            const int ch = tid + i * 256;
            const int row = ch >> 3;
            const int c8  = (ch & 7) << 3;
            CP_ASYNC16(vD + (row * STR + c8) * 2, vS + (size_t)row * DHEAD + c8);
        }
        CP_COMMIT();
    };

    cptile(0, 0);

    for (int kt = 0; kt < nkt; ++kt) {
        const int buf = kt & 1;
        if (kt + 1 < nkt) { cptile(kt + 1, (kt + 1) & 1); CP_WAIT_1(); }
        else              { CP_WAIT_0(); }
        __syncthreads();

        const uint32_t kAddr = smb + (uint32_t)buf * TBUF + (brow * STR + bcol) * 2;
        const uint32_t vAddr = smb + 2 * TBUF + (uint32_t)buf * TBUF
                             + (vtr * STR + vdc) * 2;

        // ---- S = (Q/8) K^T ----
        float sacc[8][4];
#pragma unroll
        for (int hh = 0; hh < 4; ++hh) {
            sacc[2*hh][0] = sacc[2*hh][1] = sacc[2*hh][2] = sacc[2*hh][3] = 0.0f;
            sacc[2*hh+1][0] = sacc[2*hh+1][1] = sacc[2*hh+1][2] = sacc[2*hh+1][3] = 0.0f;
#pragma unroll
            for (int ks = 0; ks < 4; ++ks) {
                uint32_t kb[4];
                ldm_x4(kb, kAddr + (hh * 16 * STR + ks * 16) * 2);
                mma16816h(sacc[2 * hh],     aq[ks], kb[0], kb[1]);
                mma16816h(sacc[2 * hh + 1], aq[ks], kb[2], kb[3]);
            }
        }

        // ---- causal mask ----
        if (kt * 64 + 63 > qb + wq * 16) {
            const int r0g = qb + wq * 16 + q, r1g = r0g + 8;
#pragma unroll
            for (int nt = 0; nt < 8; ++nt) {
                const int c0g = kt * 64 + 8 * nt + 2 * cc;
                if (c0g     > r0g) sacc[nt][0] = -INFINITY;
                if (c0g + 1 > r0g) sacc[nt][1] = -INFINITY;
                if (c0g     > r1g) sacc[nt][2] = -INFINITY;
                if (c0g + 1 > r1g) sacc[nt][3] = -INFINITY;
            }
        }

        // ---- online softmax ----
        float cm0 = -INFINITY, cm1 = -INFINITY;
#pragma unroll
        for (int nt = 0; nt < 8; ++nt) {
            cm0 = fmaxf(cm0, fmaxf(sacc[nt][0], sacc[nt][1]));
            cm1 = fmaxf(cm1, fmaxf(sacc[nt][2], sacc[nt][3]));
        }
        cm0 = fmaxf(cm0, __shfl_xor_sync(0xffffffffu, cm0, 1));
        cm0 = fmaxf(cm0, __shfl_xor_sync(0xffffffffu, cm0, 2));
        cm1 = fmaxf(cm1, __shfl_xor_sync(0xffffffffu, cm1, 1));
        cm1 = fmaxf(cm1, __shfl_xor_sync(0xffffffffu, cm1, 2));

        const float mn0 = fmaxf(m0, cm0), mn1 = fmaxf(m1, cm1);
        const float corr0 = __expf(m0 - mn0), corr1 = __expf(m1 - mn1);

        uint32_t ph[8][2];
        float ps0 = 0.0f, ps1 = 0.0f;
#pragma unroll
        for (int nt = 0; nt < 8; ++nt) {
            const float pp0 = __expf(sacc[nt][0] - mn0);
            const float pp1 = __expf(sacc[nt][1] - mn0);
            const float pp2 = __expf(sacc[nt][2] - mn1);
            const float pp3 = __expf(sacc[nt][3] - mn1);
            ps0 += pp0 + pp1; ps1 += pp2 + pp3;
            ph[nt][0] = pack_h2(pp0, pp1);
            ph[nt][1] = pack_h2(pp2, pp3);
            oacc[nt][0] *= corr0; oacc[nt][1] *= corr0;
            oacc[nt][2] *= corr1; oacc[nt][3] *= corr1;
        }
        l0 = l0 * corr0 + ps0;
        l1 = l1 * corr1 + ps1;
        m0 = mn0; m1 = mn1;

        // ---- O += P V  (V frags via ldmatrix.trans on [t][d] tiles) ----
#pragma unroll
        for (int g = 0; g < 4; ++g) {
            uint32_t ap[4] = { ph[2 * g][0], ph[2 * g][1],
                               ph[2 * g + 1][0], ph[2 * g + 1][1] };
#pragma unroll
            for (int hh = 0; hh < 4; ++hh) {
                uint32_t vb4[4];
                ldm_x4_t(vb4, vAddr + (g * 16 * STR + hh * 16) * 2);
                mma16816h(oacc[2 * hh],     ap, vb4[0], vb4[1]);
                mma16816h(oacc[2 * hh + 1], ap, vb4[2], vb4[3]);
            }
        }
        __syncthreads();
    }

    // ---- epilogue: fp16 output ----
    l0 += __shfl_xor_sync(0xffffffffu, l0, 1);
    l0 += __shfl_xor_sync(0xffffffffu, l0, 2);
    l1 += __shfl_xor_sync(0xffffffffu, l1, 1);
    l1 += __shfl_xor_sync(0xffffffffu, l1, 2);
    const float inv0 = 1.0f / l0, inv1 = 1.0f / l1;

    __half* ob = out + (size_t)(b * SEQ + qb + wq * 16 + q) * DMODEL + h * DHEAD;
#pragma unroll
    for (int nt = 0; nt < 8; ++nt) {
        *reinterpret_cast<uint32_t*>(&ob[8 * nt + 2 * cc]) =
            pack_h2(oacc[nt][0] * inv0, oacc[nt][1] * inv0);
        *reinterpret_cast<uint32_t*>(&ob[(size_t)8 * DMODEL + 8 * nt + 2 * cc]) =
            pack_h2(oacc[nt][2] * inv1, oacc[nt][3] * inv1);
    }
}

// ---------------------------------------------------------------------------
extern "C" void kernel_launch(void* const* d_in, const int* in_sizes, int n_in,
                              void* d_out, int out_size)
{
    const float* x     = (const float*)d_in[0];
    const float* W_qkv = (const float*)d_in[1];
    const float* W_out = (const float*)d_in[2];
    float* out = (float*)d_out;

    __half *xh, *qkh, *attnh, *wqkvTh, *woutTh, *vh;
    cudaGetSymbolAddress((void**)&xh,     g_xh);
    cudaGetSymbolAddress((void**)&qkh,    g_qkh);
    cudaGetSymbolAddress((void**)&attnh,  g_attnh);
    cudaGetSymbolAddress((void**)&wqkvTh, g_wqkvTh);
    cudaGetSymbolAddress((void**)&woutTh, g_woutTh);
    cudaGetSymbolAddress((void**)&vh,     g_vh);

    cudaFuncSetAttribute(gemm_fp16_kernel,
                         cudaFuncAttributeMaxDynamicSharedMemorySize, GEMM_SMEM);
    cudaFuncSetAttribute(attn_mma_kernel,
                         cudaFuncAttributeMaxDynamicSharedMemorySize, ATTN_SMEM);

    // Pre-passes
    const int n8 = MROWS * DMODEL / 8;
    cvt_fp16_kernel<<<n8 / 256, 256>>>((const float4*)x, (uint2*)xh, n8);
    transpose_fp16_kernel<<<dim3(QKVCOLS / 32, DMODEL / 32), dim3(32, 8)>>>(
        W_qkv, wqkvTh, DMODEL, QKVCOLS);
    transpose_fp16_kernel<<<dim3(DMODEL / 32, DMODEL / 32), dim3(32, 8)>>>(
        W_out, woutTh, DMODEL, DMODEL);

    // 1) QKV projection (fp16 MMA): fp16 Q/K + fp16 V ([b][h][t][d])
    gemm_fp16_kernel<<<dim3(QKVCOLS / 128, MROWS / 128), 256, GEMM_SMEM>>>(
        xh, wqkvTh, nullptr, qkh, vh, MROWS, QKVCOLS, DMODEL, 1);

    // 2) Flash attention (fp16 QK^T + fp16 PV, trans-ldmatrix V) -> fp16 out
    attn_mma_kernel<<<dim3(SEQ / 128, NHEADS, BSZ), 256, ATTN_SMEM>>>(qkh, vh, attnh);

    // 3) Output projection (fp16 MMA) -> f32 result
    gemm_fp16_kernel<<<dim3(DMODEL / 128, MROWS / 128), 256, GEMM_SMEM>>>(
        attnh, woutTh, out, nullptr, nullptr, MROWS, DMODEL, DMODEL, 0);
}